// round 11
// baseline (speedup 1.0000x reference)
#include <cuda_runtime.h>
#include <cuda_fp16.h>
#include <cstdint>

#define NS 512
#define NK 64
#define NVEC 65536
#define M_TILE 256
#define NCTA (NVEC / M_TILE)      /* 256 */
#define NTHR 256

#define OFF_Z      (NVEC*NK)
#define OFF_COMMIT (OFF_Z + NVEC)
#define OFF_CB     (OFF_COMMIT + 1)
#define OFF_ERR    (OFF_CB + 1)

/* dynamic smem: A region [0,65536) (2 planes * 256 rows * 128B) is reused
   as the 2x16KB B double-buffer after A fragments go register-resident. */
#define SM_A    0
#define SM_B    0
#define SM_SCN  65536       /* 512*4 */
#define SM_VN   67584       /* 256*4 */
#define SM_RED  68608       /* 8*4 */
#define SM_TOT  68672

__device__ float  g_c[NS * NK];
__device__ float  g_cnh[NS];
__device__ __half g_ch[2][NS * NK];      // codebook fp16 planes (h0, h1)
__device__ float  g_partial[NCTA];
__device__ int    g_done;

__device__ __forceinline__ uint32_t smem_u32(const void* p) {
    uint32_t a;
    asm("{ .reg .u64 t; cvta.to.shared.u64 t, %1; cvt.u32.u64 %0, t; }" : "=r"(a) : "l"(p));
    return a;
}
__device__ __forceinline__ void ldsm_x4(uint32_t* r, uint32_t a) {
    asm volatile("ldmatrix.sync.aligned.m8n8.x4.shared.b16 {%0,%1,%2,%3}, [%4];"
                 : "=r"(r[0]), "=r"(r[1]), "=r"(r[2]), "=r"(r[3]) : "r"(a));
}
__device__ __forceinline__ void mma16816(float* c, const uint32_t* a, const uint32_t* b) {
    asm volatile("mma.sync.aligned.m16n8k16.row.col.f32.f16.f16.f32 "
                 "{%0,%1,%2,%3}, {%4,%5,%6,%7}, {%8,%9}, {%0,%1,%2,%3};"
                 : "+f"(c[0]), "+f"(c[1]), "+f"(c[2]), "+f"(c[3])
                 : "r"(a[0]), "r"(a[1]), "r"(a[2]), "r"(a[3]), "r"(b[0]), "r"(b[1]));
}
__device__ __forceinline__ void cpa16(uint32_t dst, const void* src) {
    asm volatile("cp.async.cg.shared.global [%0], [%1], 16;" :: "r"(dst), "l"(src));
}
#define CPA_COMMIT() asm volatile("cp.async.commit_group;" ::: "memory")
#define CPA_WAIT(n)  asm volatile("cp.async.wait_group %0;" :: "n"(n) : "memory")

__device__ __forceinline__ void hsplit(float x, __half& h0, __half& h1) {
    h0 = __float2half_rn(x);
    h1 = __float2half_rn(x - __half2float(h0));
}

// ---------------------------------------------------------------------------
// Kernel 1: codebook -> fp32 + half-norms + fp16 planes; reset done counter.
// ---------------------------------------------------------------------------
__global__ void __launch_bounds__(128) vq_prep_code(const float* __restrict__ c_sum,
                                                    const float* __restrict__ c_count) {
    if (blockIdx.x == 0 && threadIdx.x == 0) g_done = 0;
    int warp = (blockIdx.x * blockDim.x + threadIdx.x) >> 5;
    int lane = threadIdx.x & 31;
    if (warp >= NS) return;
    float inv = 1.0f / fmaxf(c_count[warp], 0.01f);
    float a = c_sum[warp * NK + lane] * inv;
    float b = c_sum[warp * NK + 32 + lane] * inv;
    g_c[warp * NK + lane] = a;
    g_c[warp * NK + 32 + lane] = b;
    __half h0, h1;
    hsplit(a, h0, h1);
    g_ch[0][warp * NK + lane] = h0;
    g_ch[1][warp * NK + lane] = h1;
    hsplit(b, h0, h1);
    g_ch[0][warp * NK + 32 + lane] = h0;
    g_ch[1][warp * NK + 32 + lane] = h1;
    float nh = a * a + b * b;
#pragma unroll
    for (int o = 16; o; o >>= 1) nh += __shfl_xor_sync(0xffffffffu, nh, o);
    if (lane == 0) g_cnh[warp] = 0.5f * nh;
}

// ---------------------------------------------------------------------------
// Kernel 2: 256 threads, 8 warps, 32 rows/warp; MMA issue reordered so
// same-accumulator dependency distance is 4 (was 2).
// ---------------------------------------------------------------------------
__global__ void __launch_bounds__(NTHR, 2) vq_mma(const float* __restrict__ vecs,
                                                  float* __restrict__ out) {
    extern __shared__ __align__(128) char smem[];
    uint32_t sb = smem_u32(smem);
    int tid = threadIdx.x;
    int wid = tid >> 5;
    int lane = tid & 31;
    int cta = blockIdx.x;

    for (int i = tid; i < NS; i += NTHR)
        reinterpret_cast<float*>(smem + SM_SCN)[i] = g_cnh[i];

    // fused A conversion: thread t owns vector row t (256 rows)
    {
        const float4* src = reinterpret_cast<const float4*>(
            vecs + ((size_t)cta * M_TILE + tid) * NK);
        float vn = 0.f;
        int rsw = tid & 7;
#pragma unroll
        for (int ch = 0; ch < 8; ch++) {
            float4 q0 = src[2 * ch], q1 = src[2 * ch + 1];
            float x[8] = {q0.x, q0.y, q0.z, q0.w, q1.x, q1.y, q1.z, q1.w};
            union { uint4 u; __half2 h[4]; } p0, p1;
#pragma unroll
            for (int j = 0; j < 4; j++) {
                __half a0, a1, b0, b1;
                hsplit(x[2 * j], a0, a1);
                hsplit(x[2 * j + 1], b0, b1);
                p0.h[j] = __halves2half2(a0, b0);
                p1.h[j] = __halves2half2(a1, b1);
                vn += x[2 * j] * x[2 * j] + x[2 * j + 1] * x[2 * j + 1];
            }
            uint32_t off = tid * 128 + ((ch ^ rsw) << 4);
            *reinterpret_cast<uint4*>(smem + SM_A + off) = p0.u;
            *reinterpret_cast<uint4*>(smem + SM_A + 32768 + off) = p1.u;
        }
        reinterpret_cast<float*>(smem + SM_VN)[tid] = vn;
    }
    __syncthreads();

    // register-resident A fragments: [plane][mtile][kstep][4] (warp: 32 rows)
    uint32_t af[2][2][4][4];
    {
        int r = lane & 15;
        int hi = lane >> 4;
#pragma unroll
        for (int p = 0; p < 2; p++)
#pragma unroll
            for (int mt = 0; mt < 2; mt++) {
                int row = wid * 32 + mt * 16 + r;
#pragma unroll
                for (int k = 0; k < 4; k++) {
                    int ch = (2 * k + hi) ^ (row & 7);
                    ldsm_x4(af[p][mt][k], sb + SM_A + p * 32768 + row * 128 + ch * 16);
                }
            }
    }
    __syncthreads();   // A region becomes B double-buffer

    auto loadB = [&](int tile, int buf) {
#pragma unroll
        for (int j = 0; j < 4; j++) {
            int i = tid + NTHR * j;
            int row = i >> 3, ch = i & 7;
            int p = row >> 6, r = row & 63;
            const __half* src = g_ch[p] + ((size_t)tile * 64 + r) * NK + ch * 8;
            cpa16(sb + SM_B + buf * 16384 + p * 8192 + r * 128 + (((ch ^ (r & 7))) << 4), src);
        }
    };
    loadB(0, 0);
    CPA_COMMIT();

    const float* scn = reinterpret_cast<const float*>(smem + SM_SCN);
    float best[4] = {-3.4e38f, -3.4e38f, -3.4e38f, -3.4e38f};
    int idx[4] = {0, 0, 0, 0};
    int brow_lo = (lane >> 4) << 3;
    int kh = (lane >> 3) & 1;

    for (int tile = 0; tile < 8; tile++) {
        if (tile < 7) { loadB(tile + 1, (tile + 1) & 1); CPA_COMMIT(); CPA_WAIT(1); }
        else CPA_WAIT(0);
        __syncthreads();
        uint32_t bbase = sb + SM_B + (tile & 1) * 16384;

#pragma unroll
        for (int npair = 0; npair < 4; npair++) {
            float acc[2][2][4] = {};          // [mtile][nbhalf][4]
            int row = npair * 16 + brow_lo + (lane & 7);
            int rsw = row & 7;
#pragma unroll
            for (int k = 0; k < 4; k++) {     // B plane 0: a0 then a1 groups
                uint32_t bf[4];
                ldsm_x4(bf, bbase + row * 128 + (((2 * k + kh) ^ rsw) << 4));
                // group 1: a0 terms into all 4 accumulators (distance 4)
                mma16816(acc[0][0], af[0][0][k], bf + 0);
                mma16816(acc[0][1], af[0][0][k], bf + 2);
                mma16816(acc[1][0], af[0][1][k], bf + 0);
                mma16816(acc[1][1], af[0][1][k], bf + 2);
                // group 2: a1 terms into all 4 accumulators
                mma16816(acc[0][0], af[1][0][k], bf + 0);
                mma16816(acc[0][1], af[1][0][k], bf + 2);
                mma16816(acc[1][0], af[1][1][k], bf + 0);
                mma16816(acc[1][1], af[1][1][k], bf + 2);
            }
#pragma unroll
            for (int k = 0; k < 4; k++) {     // B plane 1: a0 term only
                uint32_t bf[4];
                ldsm_x4(bf, bbase + 8192 + row * 128 + (((2 * k + kh) ^ rsw) << 4));
                mma16816(acc[0][0], af[0][0][k], bf + 0);
                mma16816(acc[0][1], af[0][0][k], bf + 2);
                mma16816(acc[1][0], af[0][1][k], bf + 0);
                mma16816(acc[1][1], af[0][1][k], bf + 2);
            }
#pragma unroll
            for (int mt = 0; mt < 2; mt++)
#pragma unroll
                for (int nb = 0; nb < 2; nb++) {
                    int ncol = tile * 64 + npair * 16 + nb * 8 + 2 * (lane & 3);
                    float s0 = scn[ncol], s1 = scn[ncol + 1];
                    float v;
                    v = acc[mt][nb][0] - s0;
                    if (v > best[2*mt])   { best[2*mt] = v;   idx[2*mt] = ncol; }
                    v = acc[mt][nb][1] - s1;
                    if (v > best[2*mt])   { best[2*mt] = v;   idx[2*mt] = ncol + 1; }
                    v = acc[mt][nb][2] - s0;
                    if (v > best[2*mt+1]) { best[2*mt+1] = v; idx[2*mt+1] = ncol; }
                    v = acc[mt][nb][3] - s1;
                    if (v > best[2*mt+1]) { best[2*mt+1] = v; idx[2*mt+1] = ncol + 1; }
                }
        }
        __syncthreads();
    }

    // quad reduce (tie -> lower index)
#pragma unroll
    for (int slot = 0; slot < 4; slot++) {
#pragma unroll
        for (int off = 1; off <= 2; off <<= 1) {
            float ob = __shfl_xor_sync(0xffffffffu, best[slot], off);
            int oi = __shfl_xor_sync(0xffffffffu, idx[slot], off);
            if (ob > best[slot] || (ob == best[slot] && oi < idx[slot])) {
                best[slot] = ob; idx[slot] = oi;
            }
        }
    }

    const float* svn = reinterpret_cast<const float*>(smem + SM_VN);
    float errsum = 0.f;
#pragma unroll
    for (int slot = 0; slot < 4; slot++) {
        int row = wid * 32 + (slot >> 1) * 16 + (slot & 1) * 8 + (lane >> 2);
        int n = cta * M_TILE + row;
        const float4* c = reinterpret_cast<const float4*>(g_c + (size_t)idx[slot] * NK);
        float4* o = reinterpret_cast<float4*>(out + (size_t)n * NK);
#pragma unroll
        for (int j = lane & 3; j < 16; j += 4) o[j] = c[j];
        if ((lane & 3) == 0) {
            float err = fmaxf(svn[row] - 2.0f * best[slot], 0.0f);
            out[OFF_Z + n] = (float)idx[slot];
            out[OFF_ERR + n] = err;
            errsum += err;
        }
    }
#pragma unroll
    for (int o = 16; o; o >>= 1) errsum += __shfl_xor_sync(0xffffffffu, errsum, o);
    float* red = reinterpret_cast<float*>(smem + SM_RED);
    if (lane == 0) red[wid] = errsum;
    __syncthreads();
    if (tid == 0)
        g_partial[cta] = ((red[0] + red[1]) + (red[2] + red[3]))
                       + ((red[4] + red[5]) + (red[6] + red[7]));

    // fused finalize: last CTA reduces all partials (fixed deterministic order)
    __shared__ int s_last;
    if (tid == 0) {
        __threadfence();
        s_last = (atomicAdd(&g_done, 1) == NCTA - 1);
    }
    __syncthreads();
    if (s_last) {
        __threadfence();
        float* fred = reinterpret_cast<float*>(smem + SM_A);
        fred[tid] = g_partial[tid];
        __syncthreads();
#pragma unroll
        for (int off = 128; off > 0; off >>= 1) {
            if (tid < off) fred[tid] += fred[tid + off];
            __syncthreads();
        }
        if (tid == 0) {
            out[OFF_COMMIT] = fred[0] * (1.0f / (float)NVEC);
            out[OFF_CB] = 0.0f;   // l_codebook is identically 0 in forward value
        }
    }
}

extern "C" void kernel_launch(void* const* d_in, const int* in_sizes, int n_in,
                              void* d_out, int out_size) {
    const float* vecs    = (const float*)d_in[0];
    const float* c_sum   = (const float*)d_in[1];
    const float* c_count = (const float*)d_in[2];
    float* out = (float*)d_out;

    cudaFuncSetAttribute(vq_mma, cudaFuncAttributeMaxDynamicSharedMemorySize, SM_TOT);

    vq_prep_code<<<128, 128>>>(c_sum, c_count);
    vq_mma<<<NCTA, NTHR, SM_TOT>>>(vecs, out);
}

// round 12
// speedup vs baseline: 1.5055x; 1.5055x over previous
#include <cuda_runtime.h>
#include <cuda_fp16.h>
#include <cstdint>

#define NS 512
#define NK 64
#define NVEC 65536
#define M_TILE 256
#define NCTA (NVEC / M_TILE)      /* 256 */
#define NTHR 256

#define OFF_Z      (NVEC*NK)
#define OFF_COMMIT (OFF_Z + NVEC)
#define OFF_CB     (OFF_COMMIT + 1)
#define OFF_ERR    (OFF_CB + 1)

/* dynamic smem: A region [0,65536) (2 planes * 256 rows * 128B) is reused
   as a 4x16KB cp.async B ring after A fragments go register-resident. */
#define SM_A    0
#define SM_B    0
#define SM_SCN  65536       /* 512*4 */
#define SM_VN   67584       /* 256*4 */
#define SM_RED  68608       /* 8*4 */
#define SM_TOT  68672

__device__ float  g_c[NS * NK];
__device__ float  g_cnh[NS];
__device__ __half g_ch[2][NS * NK];      // codebook fp16 planes (h0, h1)
__device__ float  g_partial[NCTA];
__device__ int    g_done;

__device__ __forceinline__ uint32_t smem_u32(const void* p) {
    uint32_t a;
    asm("{ .reg .u64 t; cvta.to.shared.u64 t, %1; cvt.u32.u64 %0, t; }" : "=r"(a) : "l"(p));
    return a;
}
__device__ __forceinline__ void ldsm_x4(uint32_t* r, uint32_t a) {
    asm volatile("ldmatrix.sync.aligned.m8n8.x4.shared.b16 {%0,%1,%2,%3}, [%4];"
                 : "=r"(r[0]), "=r"(r[1]), "=r"(r[2]), "=r"(r[3]) : "r"(a));
}
__device__ __forceinline__ void mma16816(float* c, const uint32_t* a, const uint32_t* b) {
    asm volatile("mma.sync.aligned.m16n8k16.row.col.f32.f16.f16.f32 "
                 "{%0,%1,%2,%3}, {%4,%5,%6,%7}, {%8,%9}, {%0,%1,%2,%3};"
                 : "+f"(c[0]), "+f"(c[1]), "+f"(c[2]), "+f"(c[3])
                 : "r"(a[0]), "r"(a[1]), "r"(a[2]), "r"(a[3]), "r"(b[0]), "r"(b[1]));
}
__device__ __forceinline__ void cpa16(uint32_t dst, const void* src) {
    asm volatile("cp.async.cg.shared.global [%0], [%1], 16;" :: "r"(dst), "l"(src));
}
#define CPA_COMMIT() asm volatile("cp.async.commit_group;" ::: "memory")
#define CPA_WAIT(n)  asm volatile("cp.async.wait_group %0;" :: "n"(n) : "memory")

__device__ __forceinline__ void hsplit(float x, __half& h0, __half& h1) {
    h0 = __float2half_rn(x);
    h1 = __float2half_rn(x - __half2float(h0));
}

// ---------------------------------------------------------------------------
// Kernel 1: codebook -> fp32 + half-norms + fp16 planes; reset done counter.
// ---------------------------------------------------------------------------
__global__ void __launch_bounds__(128) vq_prep_code(const float* __restrict__ c_sum,
                                                    const float* __restrict__ c_count) {
    if (blockIdx.x == 0 && threadIdx.x == 0) g_done = 0;
    int warp = (blockIdx.x * blockDim.x + threadIdx.x) >> 5;
    int lane = threadIdx.x & 31;
    if (warp >= NS) return;
    float inv = 1.0f / fmaxf(c_count[warp], 0.01f);
    float a = c_sum[warp * NK + lane] * inv;
    float b = c_sum[warp * NK + 32 + lane] * inv;
    g_c[warp * NK + lane] = a;
    g_c[warp * NK + 32 + lane] = b;
    __half h0, h1;
    hsplit(a, h0, h1);
    g_ch[0][warp * NK + lane] = h0;
    g_ch[1][warp * NK + lane] = h1;
    hsplit(b, h0, h1);
    g_ch[0][warp * NK + 32 + lane] = h0;
    g_ch[1][warp * NK + 32 + lane] = h1;
    float nh = a * a + b * b;
#pragma unroll
    for (int o = 16; o; o >>= 1) nh += __shfl_xor_sync(0xffffffffu, nh, o);
    if (lane == 0) g_cnh[warp] = 0.5f * nh;
}

// ---------------------------------------------------------------------------
// Kernel 2: 256 threads, 8 warps, 32 rows/warp (R10 inner loop), with a
// 4-stage cp.async B ring, prefetch distance 2, one barrier per tile.
// ---------------------------------------------------------------------------
__global__ void __launch_bounds__(NTHR, 2) vq_mma(const float* __restrict__ vecs,
                                                  float* __restrict__ out) {
    extern __shared__ __align__(128) char smem[];
    uint32_t sb = smem_u32(smem);
    int tid = threadIdx.x;
    int wid = tid >> 5;
    int lane = tid & 31;
    int cta = blockIdx.x;

    for (int i = tid; i < NS; i += NTHR)
        reinterpret_cast<float*>(smem + SM_SCN)[i] = g_cnh[i];

    // fused A conversion: thread t owns vector row t (256 rows)
    {
        const float4* src = reinterpret_cast<const float4*>(
            vecs + ((size_t)cta * M_TILE + tid) * NK);
        float vn = 0.f;
        int rsw = tid & 7;
#pragma unroll
        for (int ch = 0; ch < 8; ch++) {
            float4 q0 = src[2 * ch], q1 = src[2 * ch + 1];
            float x[8] = {q0.x, q0.y, q0.z, q0.w, q1.x, q1.y, q1.z, q1.w};
            union { uint4 u; __half2 h[4]; } p0, p1;
#pragma unroll
            for (int j = 0; j < 4; j++) {
                __half a0, a1, b0, b1;
                hsplit(x[2 * j], a0, a1);
                hsplit(x[2 * j + 1], b0, b1);
                p0.h[j] = __halves2half2(a0, b0);
                p1.h[j] = __halves2half2(a1, b1);
                vn += x[2 * j] * x[2 * j] + x[2 * j + 1] * x[2 * j + 1];
            }
            uint32_t off = tid * 128 + ((ch ^ rsw) << 4);
            *reinterpret_cast<uint4*>(smem + SM_A + off) = p0.u;
            *reinterpret_cast<uint4*>(smem + SM_A + 32768 + off) = p1.u;
        }
        reinterpret_cast<float*>(smem + SM_VN)[tid] = vn;
    }
    __syncthreads();

    // register-resident A fragments: [plane][mtile][kstep][4] (warp: 32 rows)
    uint32_t af[2][2][4][4];
    {
        int r = lane & 15;
        int hi = lane >> 4;
#pragma unroll
        for (int p = 0; p < 2; p++)
#pragma unroll
            for (int mt = 0; mt < 2; mt++) {
                int row = wid * 32 + mt * 16 + r;
#pragma unroll
                for (int k = 0; k < 4; k++) {
                    int ch = (2 * k + hi) ^ (row & 7);
                    ldsm_x4(af[p][mt][k], sb + SM_A + p * 32768 + row * 128 + ch * 16);
                }
            }
    }
    __syncthreads();   // A region becomes the 4-stage B ring

    auto loadB = [&](int tile, int buf) {
#pragma unroll
        for (int j = 0; j < 4; j++) {
            int i = tid + NTHR * j;
            int row = i >> 3, ch = i & 7;
            int p = row >> 6, r = row & 63;
            const __half* src = g_ch[p] + ((size_t)tile * 64 + r) * NK + ch * 8;
            cpa16(sb + SM_B + buf * 16384 + p * 8192 + r * 128 + (((ch ^ (r & 7))) << 4), src);
        }
    };
    loadB(0, 0); CPA_COMMIT();
    loadB(1, 1); CPA_COMMIT();

    const float* scn = reinterpret_cast<const float*>(smem + SM_SCN);
    float best[4] = {-3.4e38f, -3.4e38f, -3.4e38f, -3.4e38f};
    int idx[4] = {0, 0, 0, 0};
    int brow_lo = (lane >> 4) << 3;
    int kh = (lane >> 3) & 1;

    for (int tile = 0; tile < 8; tile++) {
        if (tile < 6) { loadB(tile + 2, (tile + 2) & 3); CPA_COMMIT(); }
        if (tile < 6)      { CPA_WAIT(2); }
        else if (tile == 6){ CPA_WAIT(1); }
        else               { CPA_WAIT(0); }
        __syncthreads();   // stage (tile&3) visible to all warps; bounds skew <1 tile
        uint32_t bbase = sb + SM_B + (tile & 3) * 16384;

#pragma unroll
        for (int npair = 0; npair < 4; npair++) {
            float acc[2][2][4] = {};          // [mtile][nbhalf][4]
            int row = npair * 16 + brow_lo + (lane & 7);
            int rsw = row & 7;
#pragma unroll
            for (int k = 0; k < 4; k++) {     // B plane 0: a0 + a1 terms
                uint32_t bf[4];
                ldsm_x4(bf, bbase + row * 128 + (((2 * k + kh) ^ rsw) << 4));
#pragma unroll
                for (int mt = 0; mt < 2; mt++) {
                    mma16816(acc[mt][0], af[0][mt][k], bf + 0);
                    mma16816(acc[mt][1], af[0][mt][k], bf + 2);
                    mma16816(acc[mt][0], af[1][mt][k], bf + 0);
                    mma16816(acc[mt][1], af[1][mt][k], bf + 2);
                }
            }
#pragma unroll
            for (int k = 0; k < 4; k++) {     // B plane 1: a0 term only
                uint32_t bf[4];
                ldsm_x4(bf, bbase + 8192 + row * 128 + (((2 * k + kh) ^ rsw) << 4));
#pragma unroll
                for (int mt = 0; mt < 2; mt++) {
                    mma16816(acc[mt][0], af[0][mt][k], bf + 0);
                    mma16816(acc[mt][1], af[0][mt][k], bf + 2);
                }
            }
#pragma unroll
            for (int mt = 0; mt < 2; mt++)
#pragma unroll
                for (int nb = 0; nb < 2; nb++) {
                    int ncol = tile * 64 + npair * 16 + nb * 8 + 2 * (lane & 3);
                    float s0 = scn[ncol], s1 = scn[ncol + 1];
                    float v;
                    v = acc[mt][nb][0] - s0;
                    if (v > best[2*mt])   { best[2*mt] = v;   idx[2*mt] = ncol; }
                    v = acc[mt][nb][1] - s1;
                    if (v > best[2*mt])   { best[2*mt] = v;   idx[2*mt] = ncol + 1; }
                    v = acc[mt][nb][2] - s0;
                    if (v > best[2*mt+1]) { best[2*mt+1] = v; idx[2*mt+1] = ncol; }
                    v = acc[mt][nb][3] - s1;
                    if (v > best[2*mt+1]) { best[2*mt+1] = v; idx[2*mt+1] = ncol + 1; }
                }
        }
        // no end-of-tile barrier: next tile's loadB targets stage (tile+3)&3,
        // which no warp (skew < 1 tile) can still be reading.
    }

    // quad reduce (tie -> lower index)
#pragma unroll
    for (int slot = 0; slot < 4; slot++) {
#pragma unroll
        for (int off = 1; off <= 2; off <<= 1) {
            float ob = __shfl_xor_sync(0xffffffffu, best[slot], off);
            int oi = __shfl_xor_sync(0xffffffffu, idx[slot], off);
            if (ob > best[slot] || (ob == best[slot] && oi < idx[slot])) {
                best[slot] = ob; idx[slot] = oi;
            }
        }
    }

    const float* svn = reinterpret_cast<const float*>(smem + SM_VN);
    float errsum = 0.f;
#pragma unroll
    for (int slot = 0; slot < 4; slot++) {
        int row = wid * 32 + (slot >> 1) * 16 + (slot & 1) * 8 + (lane >> 2);
        int n = cta * M_TILE + row;
        const float4* c = reinterpret_cast<const float4*>(g_c + (size_t)idx[slot] * NK);
        float4* o = reinterpret_cast<float4*>(out + (size_t)n * NK);
#pragma unroll
        for (int j = lane & 3; j < 16; j += 4) o[j] = c[j];
        if ((lane & 3) == 0) {
            float err = fmaxf(svn[row] - 2.0f * best[slot], 0.0f);
            out[OFF_Z + n] = (float)idx[slot];
            out[OFF_ERR + n] = err;
            errsum += err;
        }
    }
#pragma unroll
    for (int o = 16; o; o >>= 1) errsum += __shfl_xor_sync(0xffffffffu, errsum, o);
    float* red = reinterpret_cast<float*>(smem + SM_RED);
    if (lane == 0) red[wid] = errsum;
    __syncthreads();
    if (tid == 0)
        g_partial[cta] = ((red[0] + red[1]) + (red[2] + red[3]))
                       + ((red[4] + red[5]) + (red[6] + red[7]));

    // fused finalize: last CTA reduces all partials (fixed deterministic order)
    __shared__ int s_last;
    if (tid == 0) {
        __threadfence();
        s_last = (atomicAdd(&g_done, 1) == NCTA - 1);
    }
    __syncthreads();
    if (s_last) {
        __threadfence();
        float* fred = reinterpret_cast<float*>(smem + SM_A);
        fred[tid] = g_partial[tid];
        __syncthreads();
#pragma unroll
        for (int off = 128; off > 0; off >>= 1) {
            if (tid < off) fred[tid] += fred[tid + off];
            __syncthreads();
        }
        if (tid == 0) {
            out[OFF_COMMIT] = fred[0] * (1.0f / (float)NVEC);
            out[OFF_CB] = 0.0f;   // l_codebook is identically 0 in forward value
        }
    }
}

extern "C" void kernel_launch(void* const* d_in, const int* in_sizes, int n_in,
                              void* d_out, int out_size) {
    const float* vecs    = (const float*)d_in[0];
    const float* c_sum   = (const float*)d_in[1];
    const float* c_count = (const float*)d_in[2];
    float* out = (float*)d_out;

    cudaFuncSetAttribute(vq_mma, cudaFuncAttributeMaxDynamicSharedMemorySize, SM_TOT);

    vq_prep_code<<<128, 128>>>(c_sum, c_count);
    vq_mma<<<NCTA, NTHR, SM_TOT>>>(vecs, out);
}